// round 8
// baseline (speedup 1.0000x reference)
#include <cuda_runtime.h>
#include <math.h>

// Problem constants (fixed by setup_inputs)
#define BB   32
#define AA   3
#define HH   64
#define WW   64
#define CC   80
#define PRED_LAST 85          // 5 + C
#define NT   2048
#define CELLS (BB*AA*HH*WW)   // 393216

#define THREADS     256
#define TGT_BLOCKS  256       // 256 blocks * 8 warps = 2048 targets
#define CONF_BLOCKS 192       // 192*256 threads * 8 cells = 393216
#define ALL_BLOCKS  (TGT_BLOCKS + CONF_BLOCKS)   // 448

// Epoch-tagged claim words: g_mask[c] = (epoch<<3)|bits; bit0=obj, bit1=kz,
// bit2=cross. Stale-epoch words read as empty -> no reset pass ever.
// Partial arrays fully rewritten every call; epoch/done restored by the
// finalize block => identical externally-visible behavior per replay.
__device__ int      g_mask[CELLS];
__device__ unsigned g_epoch;
__device__ unsigned g_done;
__device__ double g_pconf[ALL_BLOCKS];
__device__ double g_pcls [ALL_BLOCKS];
__device__ double g_pxywh[ALL_BLOCKS];
__device__ int    g_pcnt [ALL_BLOCKS];   // (n_obj<<20)|(n_kz<<10)|n_cross

__device__ __forceinline__ float softplusf(float x) {
    return fmaxf(x, 0.0f) + log1pf(expf(-fabsf(x)));
}
__device__ __forceinline__ float wsumf(float v) {
    #pragma unroll
    for (int o = 16; o > 0; o >>= 1) v += __shfl_down_sync(0xFFFFFFFFu, v, o);
    return v;
}
__device__ __forceinline__ int wsumi(int v) {
    #pragma unroll
    for (int o = 16; o > 0; o >>= 1) v += __shfl_down_sync(0xFFFFFFFFu, v, o);
    return v;
}

// Claim `bit` on cell c for this epoch; returns bits present BEFORE the claim
// (0 if the stored word is from an older epoch).
__device__ __forceinline__ int claim_bits(int c, int bit, unsigned epoch) {
    int* addr = &g_mask[c];
    const unsigned tag = epoch << 3;
    unsigned old = (unsigned)*addr;
    while (true) {
        const unsigned cur = ((old >> 3) == epoch) ? (old & 7u) : 0u;
        const unsigned nv  = tag | cur | (unsigned)bit;
        const unsigned got = (unsigned)atomicCAS(addr, (int)old, (int)nv);
        if (got == old) return (int)cur;
        old = got;
    }
}

// ---------------------------------------------------------------------------
// ONE kernel, block-specialized:
//   blocks [0, 256):   target blocks — 8 warps, one target each. IoU argmax,
//                      epoch-tagged claims + order-independent conf
//                      corrections, xywh MSE, 80-ch cls BCE.
//   blocks [256, 448): conf blocks — pure gather stream of pred[...,4],
//                      NO mask access (base term covers every cell).
//   last-done block:   reduce 448 partials, write loss, bump epoch.
// ---------------------------------------------------------------------------
__global__ void __launch_bounds__(THREADS) k_fused(const float* __restrict__ pred,
                                                   const float* __restrict__ target,
                                                   const float* __restrict__ anchors,
                                                   float* __restrict__ out)
{
    const int tid  = threadIdx.x;
    const int lane = tid & 31;
    const int wrp  = tid >> 5;

    float conf = 0.0f, cls = 0.0f, xywh = 0.0f;
    int n_obj = 0, n_kz = 0, n_cross = 0;

    if (blockIdx.x >= TGT_BLOCKS) {
        // ================= conf block: clean base stream =================
        const int cid    = blockIdx.x - TGT_BLOCKS;
        const int base   = cid * THREADS + tid;
        const int stride = CONF_BLOCKS * THREADS;   // 49152

        float pc[8];
        #pragma unroll
        for (int k = 0; k < 8; ++k)
            pc[k] = __ldg(pred + (base + k * stride) * PRED_LAST + 4);
        #pragma unroll
        for (int k = 0; k < 8; ++k) conf += softplusf(pc[k]);
    } else {
        // ================= target block: one warp per target =============
        const unsigned epoch = g_epoch;
        const int n = blockIdx.x * 8 + wrp;

        const float* t = target + n * 6;
        const float tb = __ldg(t + 0);
        const float tl = __ldg(t + 1);
        const float tx = __ldg(t + 2) * (float)HH;
        const float ty = __ldg(t + 3) * (float)HH;
        const float tw = __ldg(t + 4) * (float)HH;
        const float th = __ldg(t + 5) * (float)HH;
        const int b   = (int)tb;
        const int lab = (int)tl;
        const int wi  = (int)tw;   // grid indices come from WH in the reference
        const int hi  = (int)th;

        float ious[AA];
        float best = -1.0f;
        int   besta = 0;
        #pragma unroll
        for (int a = 0; a < AA; ++a) {
            const float aw = __ldg(anchors + 2*a), ah = __ldg(anchors + 2*a + 1);
            const float inter = fminf(aw, tw) * fminf(ah, th);
            const float iou = inter / (aw*ah + tw*th - inter);
            ious[a] = iou;
            if (iou > best) { best = iou; besta = a; }
        }
        const int cell_best = ((b*AA + besta)*HH + hi)*WW + wi;
        const float* prow = pred + (long long)cell_best * PRED_LAST;

        // claims + conf corrections (lanes 0-2: kz per anchor, lane 3: obj)
        if (lane < 3) {
            if (ious[lane] > 0.5f) {
                const int c = ((b*AA + lane)*HH + hi)*WW + wi;
                const float pc = __ldg(pred + c * PRED_LAST + 4);
                const int prev = claim_bits(c, 2, epoch);
                if (!(prev & 2)) {
                    conf -= softplusf(pc);
                    n_kz = 1;
                    if (prev & 1) {   // later of the (obj,kz) pair applies cross
                        const int p2 = claim_bits(c, 4, epoch);
                        if (!(p2 & 4)) { conf += softplusf(pc); n_cross = 1; }
                    }
                }
            }
        } else if (lane == 3) {
            const int c = cell_best;
            const float pc = __ldg(prow + 4);
            const int prev = claim_bits(c, 1, epoch);
            if (!(prev & 1)) {
                conf -= pc;        // base had sp(pc) counted as noobj; obj term = sp - pc
                n_obj = 1;
                if (prev & 2) {
                    const int p2 = claim_bits(c, 4, epoch);
                    if (!(p2 & 4)) { conf += softplusf(pc); n_cross = 1; }
                }
            }
            const float fx = tx - floorf(tx);
            const float fy = ty - floorf(ty);
            const float lw = logf(tw / __ldg(anchors + 2*besta));
            const float lh = logf(th / __ldg(anchors + 2*besta + 1));
            const float d0 = prow[0] - fx, d1 = prow[1] - fy;
            const float d2 = prow[2] - lw, d3 = prow[3] - lh;
            xywh = d0*d0 + d1*d1 + d2*d2 + d3*d3;
        }

        // cls BCE over one-hot: lanes cover channels c, c+32, c+64
        const float* pcls = prow + 5;
        const float x0 = __ldg(pcls + lane);
        const float x1 = __ldg(pcls + lane + 32);
        const float x2 = (lane < 16) ? __ldg(pcls + lane + 64) : 0.0f;
        cls = softplusf(x0) + softplusf(x1);
        if (lane < 16) cls += softplusf(x2);
        if (lab < 32)      { if (lane == lab)      cls -= x0; }
        else if (lab < 64) { if (lane == lab - 32) cls -= x1; }
        else               { if (lane == lab - 64) cls -= x2; }
    }

    // ---- block reduction -> per-block partials ----
    conf = wsumf(conf);
    cls  = wsumf(cls);
    xywh = wsumf(xywh);
    int cnt = wsumi((n_obj << 20) | (n_kz << 10) | n_cross);

    __shared__ float sc[8], sl[8], sx[8];
    __shared__ int   si[8];
    if (lane == 0) { sc[wrp] = conf; sl[wrp] = cls; sx[wrp] = xywh; si[wrp] = cnt; }
    __syncthreads();
    if (tid == 0) {
        double dc = 0.0, dl = 0.0, dx = 0.0; int ci = 0;
        #pragma unroll
        for (int w = 0; w < 8; ++w) { dc += (double)sc[w]; dl += (double)sl[w]; dx += (double)sx[w]; ci += si[w]; }
        g_pconf[blockIdx.x] = dc;
        g_pcls [blockIdx.x] = dl;
        g_pxywh[blockIdx.x] = dx;
        g_pcnt [blockIdx.x] = ci;
    }

    // ---- last-block-done finalize ----
    __threadfence();
    __syncthreads();
    __shared__ int is_last;
    if (tid == 0) {
        const unsigned v = atomicAdd(&g_done, 1u);
        is_last = (v == ALL_BLOCKS - 1u);
    }
    __syncthreads();
    if (!is_last) return;
    __threadfence();   // acquire all other blocks' partial stores

    const volatile double* vpc = (const volatile double*)g_pconf;
    const volatile double* vpl = (const volatile double*)g_pcls;
    const volatile double* vpx = (const volatile double*)g_pxywh;
    const volatile int*    vpi = (const volatile int*)g_pcnt;

    // 448 partials, 2 per thread (tid and tid+256; tid+256 valid for tid<192)
    double dc = vpc[tid], dl = vpl[tid], dx = vpx[tid];
    int c0 = vpi[tid];
    long long no  = (long long)((c0 >> 20) & 0x3FF);
    long long nk  = (long long)((c0 >> 10) & 0x3FF);
    long long ncr = (long long)( c0        & 0x3FF);
    if (tid < ALL_BLOCKS - 256) {
        dc += vpc[tid + 256]; dl += vpl[tid + 256]; dx += vpx[tid + 256];
        const int c1 = vpi[tid + 256];
        no  += (c1 >> 20) & 0x3FF;
        nk  += (c1 >> 10) & 0x3FF;
        ncr +=  c1        & 0x3FF;
    }
    long long nn = (no << 40) | (nk << 20) | ncr;   // sums < 2^20 per field

    #pragma unroll
    for (int o = 16; o > 0; o >>= 1) {
        dc += __shfl_down_sync(0xFFFFFFFFu, dc, o);
        dl += __shfl_down_sync(0xFFFFFFFFu, dl, o);
        dx += __shfl_down_sync(0xFFFFFFFFu, dx, o);
        nn += __shfl_down_sync(0xFFFFFFFFu, nn, o);
    }
    __shared__ double wc[8], wl[8], wx[8];
    __shared__ long long wn[8];
    if (lane == 0) { wc[wrp] = dc; wl[wrp] = dl; wx[wrp] = dx; wn[wrp] = nn; }
    __syncthreads();

    if (tid == 0) {
        double c = 0.0, l = 0.0, x = 0.0; long long nAll = 0;
        #pragma unroll
        for (int w = 0; w < 8; ++w) { c += wc[w]; l += wl[w]; x += wx[w]; nAll += wn[w]; }
        const double nobj   = (double)((nAll >> 40) & 0xFFFFF);
        const double nkz    = (double)((nAll >> 20) & 0xFFFFF);
        const double ncross = (double)( nAll        & 0xFFFFF);
        const double n_noobj = (double)CELLS - nobj - nkz + ncross;
        out[0] = (float)(x / ((double)NT * 4.0)
                       + c / (nobj + n_noobj)
                       + l / ((double)NT * (double)CC));
        g_epoch = g_epoch + 1;   // fresh epoch next launch (no mask reset)
        g_done  = 0;
    }
}

extern "C" void kernel_launch(void* const* d_in, const int* in_sizes, int n_in,
                              void* d_out, int out_size)
{
    const float* pred    = (const float*)d_in[0];
    const float* target  = (const float*)d_in[1];
    const float* anchors = (const float*)d_in[2];
    float* out = (float*)d_out;

    k_fused<<<ALL_BLOCKS, THREADS>>>(pred, target, anchors, out);
}

// round 9
// speedup vs baseline: 1.5823x; 1.5823x over previous
#include <cuda_runtime.h>
#include <cuda_bf16.h>
#include <math.h>

// Problem constants (fixed by setup_inputs)
#define BB   32
#define AA   3
#define HH   64
#define WW   64
#define CC   80
#define PRED_LAST 85          // 5 + C
#define NT   2048
#define CELLS (BB*AA*HH*WW)   // 393216

#define CONF_THREADS 256
#define CONF_BLOCKS  768      // 768*256 threads * 2 cells = 393216
#define CONF_CPT     2

// Scratch: zero-initialized device globals. Each kernel that consumes them
// resets them in the same pass (graph-replay safe, deterministic).
__device__ unsigned char g_obj[CELLS];       // obj mask
__device__ unsigned char g_kz[CELLS];        // "keep product is zero" sticky flag
__device__ double g_acc[4];                  // 0:conf 1:xywh 2:cls
__device__ unsigned long long g_cnt;         // (n_obj<<32) | n_noobj

__device__ __forceinline__ float softplusf(float x) {
    return fmaxf(x, 0.0f) + log1pf(expf(-fabsf(x)));
}

__device__ __forceinline__ float warp_sum(float v) {
    #pragma unroll
    for (int o = 16; o > 0; o >>= 1) v += __shfl_down_sync(0xFFFFFFFFu, v, o);
    return v;
}

// ---------------------------------------------------------------------------
// Kernel 1: one WARP per target; 8 targets per 256-thread block.  (R2-exact)
// ---------------------------------------------------------------------------
__global__ void k_targets(const float* __restrict__ pred,
                          const float* __restrict__ target,
                          const float* __restrict__ anchors)
{
    const int tid  = threadIdx.x;
    const int lane = tid & 31;
    const int wrp  = tid >> 5;
    const int n    = blockIdx.x * 8 + wrp;

    const float* t = target + n * 6;
    const float tb = __ldg(t + 0);
    const float tl = __ldg(t + 1);
    const float tx = __ldg(t + 2) * (float)HH;
    const float ty = __ldg(t + 3) * (float)HH;
    const float tw = __ldg(t + 4) * (float)HH;
    const float th = __ldg(t + 5) * (float)HH;

    const int b   = (int)tb;
    const int lab = (int)tl;
    const int wi  = (int)tw;   // grid indices come from WH in the reference
    const int hi  = (int)th;

    // IoU vs 3 anchors; argmax with first-max tie-break (strict >)
    float ious[AA];
    float best = -1.0f;
    int   besta = 0;
    #pragma unroll
    for (int a = 0; a < AA; ++a) {
        const float aw = __ldg(anchors + 2*a), ah = __ldg(anchors + 2*a + 1);
        const float inter = fminf(aw, tw) * fminf(ah, th);
        const float iou = inter / (aw*ah + tw*th - inter);
        ious[a] = iou;
        if (iou > best) { best = iou; besta = a; }
    }

    const int cell_best = ((b*AA + besta)*HH + hi)*WW + wi;
    const float* prow = pred + (long long)cell_best * PRED_LAST;

    float xywh = 0.0f;
    if (lane == 0) {
        #pragma unroll
        for (int a = 0; a < AA; ++a) {
            if (ious[a] > 0.5f) g_kz[((b*AA + a)*HH + hi)*WW + wi] = 1;
        }
        g_obj[cell_best] = 1;

        const float fx = tx - floorf(tx);
        const float fy = ty - floorf(ty);
        const float lw = logf(tw / __ldg(anchors + 2*besta));
        const float lh = logf(th / __ldg(anchors + 2*besta + 1));
        const float d0 = prow[0] - fx, d1 = prow[1] - fy;
        const float d2 = prow[2] - lw, d3 = prow[3] - lh;
        xywh = d0*d0 + d1*d1 + d2*d2 + d3*d3;
    }

    // cls BCE over one-hot: 80 channels -> lanes handle c, c+32, c+64
    const float* pcls = prow + 5;
    const float x0 = __ldg(pcls + lane);
    const float x1 = __ldg(pcls + lane + 32);
    const float x2 = (lane < 16) ? __ldg(pcls + lane + 64) : 0.0f;

    float s = softplusf(x0) + softplusf(x1);
    if (lane < 16) s += softplusf(x2);
    if (lane == (lab & 31) && (lab >> 5) == 0) s -= x0;
    if (lane == (lab - 32)) s -= x1;
    if (lane == (lab - 64)) s -= x2;

    s = warp_sum(s);   // lane 0 holds warp cls sum

    __shared__ float scl[8];
    __shared__ float sxy[8];
    if (lane == 0) { scl[wrp] = s; sxy[wrp] = xywh; }
    __syncthreads();
    if (tid == 0) {
        float cs = 0.0f, xs = 0.0f;
        #pragma unroll
        for (int w = 0; w < 8; ++w) { cs += scl[w]; xs += sxy[w]; }
        atomicAdd(&g_acc[2], (double)cs);
        atomicAdd(&g_acc[1], (double)xs);
    }
}

// ---------------------------------------------------------------------------
// Kernel 2: full-grid conf term. GEOMETRY CHANGE ONLY vs R2 champion:
// 768 blocks x 256 threads x 2 cells (was 192 x 256 x 8) -> 4x warps/SM
// for latency hiding. Inner code identical; masks read + reset in-pass.
// ---------------------------------------------------------------------------
__global__ void __launch_bounds__(CONF_THREADS) k_conf(const float* __restrict__ pred)
{
    const int base   = blockIdx.x * CONF_THREADS + threadIdx.x;
    const int stride = CONF_BLOCKS * CONF_THREADS;   // 196608

    float pc[CONF_CPT];
    unsigned char o[CONF_CPT], kz[CONF_CPT];
    #pragma unroll
    for (int k = 0; k < CONF_CPT; ++k) {
        const int c = base + k * stride;
        pc[k] = __ldg(pred + c * PRED_LAST + 4);
    }
    #pragma unroll
    for (int k = 0; k < CONF_CPT; ++k) {
        const int c = base + k * stride;
        o[k]  = g_obj[c];
        kz[k] = g_kz[c];
    }

    float conf = 0.0f;
    int n_o = 0, n_n = 0;
    #pragma unroll
    for (int k = 0; k < CONF_CPT; ++k) {
        const int c = base + k * stride;
        if (o[k] | kz[k]) { g_obj[c] = 0; g_kz[c] = 0; }   // reset touched cells
        const float sp = softplusf(pc[k]);
        if (o[k])        { conf += sp - pc[k]; n_o++; }     // bce(pc, 1)
        else if (!kz[k]) { conf += sp;         n_n++; }     // bce(pc, 0)
    }

    // block reduction: warp shuffle -> smem -> one atomic pair per block
    conf = warp_sum(conf);
    int cnt = (n_o << 16) | n_n;
    #pragma unroll
    for (int off = 16; off > 0; off >>= 1) cnt += __shfl_down_sync(0xFFFFFFFFu, cnt, off);

    __shared__ float sc[8];
    __shared__ int   si[8];
    const int lane = threadIdx.x & 31, wrp = threadIdx.x >> 5;
    if (lane == 0) { sc[wrp] = conf; si[wrp] = cnt; }
    __syncthreads();
    if (threadIdx.x == 0) {
        float cs = 0.0f; int ci = 0;
        #pragma unroll
        for (int w = 0; w < 8; ++w) { cs += sc[w]; ci += si[w]; }
        atomicAdd(&g_acc[0], (double)cs);
        const unsigned long long packed =
            ((unsigned long long)(unsigned)(ci >> 16) << 32) |
            (unsigned long long)(unsigned)(ci & 0xFFFF);
        atomicAdd(&g_cnt, packed);
    }
}

// ---------------------------------------------------------------------------
// Kernel 3: finalize + reset accumulators for the next replay.  (R2-exact)
// ---------------------------------------------------------------------------
__global__ void k_final(float* __restrict__ out)
{
    const double conf = g_acc[0];
    const double xywh = g_acc[1];
    const double cls  = g_acc[2];
    const unsigned long long cnt = g_cnt;
    const double n_obj   = (double)(cnt >> 32);
    const double n_noobj = (double)(cnt & 0xFFFFFFFFull);

    const double loss = xywh / ((double)NT * 4.0)
                      + conf / (n_obj + n_noobj)
                      + cls  / ((double)NT * (double)CC);
    out[0] = (float)loss;

    g_acc[0] = 0.0; g_acc[1] = 0.0; g_acc[2] = 0.0;
    g_cnt = 0ull;
}

extern "C" void kernel_launch(void* const* d_in, const int* in_sizes, int n_in,
                              void* d_out, int out_size)
{
    const float* pred    = (const float*)d_in[0];
    const float* target  = (const float*)d_in[1];
    const float* anchors = (const float*)d_in[2];
    float* out = (float*)d_out;

    k_targets<<<NT / 8, 256>>>(pred, target, anchors);
    k_conf<<<CONF_BLOCKS, CONF_THREADS>>>(pred);
    k_final<<<1, 1>>>(out);
}